// round 2
// baseline (speedup 1.0000x reference)
#include <cuda_runtime.h>
#include <cstdint>

#define NODES 100000
#define FEAT  128

// ---------------- scratch (static device memory; no allocation) ----------------
__device__ float g_agg [(size_t)NODES * FEAT];
__device__ float g_bufA[(size_t)NODES * FEAT];
__device__ float g_bufB[(size_t)NODES * FEAT];
__device__ float g_deg [NODES];
__device__ float g_invd[NODES];

// ---------------- degree ----------------
__global__ void deg_kernel(const int* __restrict__ dst, float* __restrict__ deg, int E) {
    int e = blockIdx.x * blockDim.x + threadIdx.x;
    if (e < E) atomicAdd(&deg[dst[e]], 1.0f);
}

__global__ void invdeg_kernel(const float* __restrict__ deg, float* __restrict__ invd, int n) {
    int i = blockIdx.x * blockDim.x + threadIdx.x;
    if (i < n) invd[i] = 1.0f / fmaxf(deg[i], 1.0f);
}

// ---------------- scatter-sum aggregation: warp per edge, float4 lanes ----------------
__global__ void agg_kernel(const float* __restrict__ feat, float* __restrict__ agg,
                           const int* __restrict__ srcIdx,
                           const int* __restrict__ dstIdx, int E) {
    int gtid = blockIdx.x * blockDim.x + threadIdx.x;
    int e    = gtid >> 5;
    int lane = gtid & 31;
    if (e >= E) return;
    int s = srcIdx[e];
    int d = dstIdx[e];
    const float4 v = *reinterpret_cast<const float4*>(feat + (size_t)s * FEAT + lane * 4);
    float* p = agg + (size_t)d * FEAT + lane * 4;
    asm volatile("red.global.add.v4.f32 [%0], {%1,%2,%3,%4};"
                 :: "l"(p), "f"(v.x), "f"(v.y), "f"(v.z), "f"(v.w)
                 : "memory");
}

// ---------------- fused SAGE layer GEMM ----------------
// out[n,j] = relu( (agg[n,:]*invd[n]) . Wl[j,:] + x[n,:] . Wr[j,:] + b[j] )
// block: 256 threads, 32 rows x 128 cols tile. thread = (colgrp 0..31)*4 cols x (warp 0..7)*4 rows.
__global__ void sage_gemm_kernel(const float* __restrict__ agg, const float* __restrict__ invd,
                                 const float* __restrict__ x,
                                 const float* __restrict__ Wl, const float* __restrict__ Wr,
                                 const float* __restrict__ b,
                                 float* __restrict__ out, int n, int do_relu) {
    extern __shared__ float sm[];
    float* WlT  = sm;                       // 128*128
    float* WrT  = sm + 16384;               // 128*128
    float* aggS = sm + 32768;               // 32*128
    float* xS   = sm + 32768 + 4096;        // 32*128

    const int tid = threadIdx.x;

    // load + transpose weights (coalesced gmem read)
    for (int i = tid; i < 16384; i += 256) {
        int j = i >> 7, k = i & 127;
        WlT[k * 128 + j] = Wl[i];
        WrT[k * 128 + j] = Wr[i];
    }

    const int row0 = blockIdx.x * 32;

    // stage 32 rows of agg (scaled by invd) and x
    for (int i = tid; i < 32 * 32; i += 256) {   // 32 rows * 32 float4
        int r = i >> 5, c4 = (i & 31);
        int row = row0 + r;
        if (row < n) {
            float iv = invd[row];
            float4 a  = *reinterpret_cast<const float4*>(agg + (size_t)row * FEAT + c4 * 4);
            float4 xv = *reinterpret_cast<const float4*>(x   + (size_t)row * FEAT + c4 * 4);
            a.x *= iv; a.y *= iv; a.z *= iv; a.w *= iv;
            *reinterpret_cast<float4*>(aggS + r * 128 + c4 * 4) = a;
            *reinterpret_cast<float4*>(xS   + r * 128 + c4 * 4) = xv;
        }
    }
    __syncthreads();

    const int cg = tid & 31;          // column group -> cols [cg*4, cg*4+4)
    const int rg = tid >> 5;          // warp id -> rows [rg*4, rg*4+4)
    const int j0 = cg * 4;
    const int r0 = rg * 4;

    float acc[4][4];
#pragma unroll
    for (int r = 0; r < 4; r++)
#pragma unroll
        for (int c = 0; c < 4; c++) acc[r][c] = 0.0f;

#pragma unroll 4
    for (int k = 0; k < 128; k++) {
        float4 wl = *reinterpret_cast<const float4*>(WlT + k * 128 + j0);
        float4 wr = *reinterpret_cast<const float4*>(WrT + k * 128 + j0);
#pragma unroll
        for (int r = 0; r < 4; r++) {
            float a  = aggS[(r0 + r) * 128 + k];
            float xv = xS[(r0 + r) * 128 + k];
            acc[r][0] += a * wl.x + xv * wr.x;
            acc[r][1] += a * wl.y + xv * wr.y;
            acc[r][2] += a * wl.z + xv * wr.z;
            acc[r][3] += a * wl.w + xv * wr.w;
        }
    }

    float4 bv = *reinterpret_cast<const float4*>(b + j0);
#pragma unroll
    for (int r = 0; r < 4; r++) {
        int row = row0 + r0 + r;
        if (row < n) {
            float4 o;
            o.x = acc[r][0] + bv.x;
            o.y = acc[r][1] + bv.y;
            o.z = acc[r][2] + bv.z;
            o.w = acc[r][3] + bv.w;
            if (do_relu) {
                o.x = fmaxf(o.x, 0.0f); o.y = fmaxf(o.y, 0.0f);
                o.z = fmaxf(o.z, 0.0f); o.w = fmaxf(o.w, 0.0f);
            }
            *reinterpret_cast<float4*>(out + (size_t)row * FEAT + j0) = o;
        }
    }
}

// ---------------- heads: 8 output channels (age 3 | sex 2 | eth 3), warp per node ----------------
__global__ void heads_kernel(const float* __restrict__ agg, const float* __restrict__ invd,
                             const float* __restrict__ h,
                             const float* __restrict__ Wal, const float* __restrict__ War, const float* __restrict__ ba,
                             const float* __restrict__ Wsl, const float* __restrict__ Wsr, const float* __restrict__ bs,
                             const float* __restrict__ Wel, const float* __restrict__ Wer, const float* __restrict__ be,
                             float* __restrict__ out, int n) {
    __shared__ float WL[8][128];
    __shared__ float WR[8][128];
    __shared__ float bias[8];
    const int tid = threadIdx.x;

    for (int i = tid; i < 3 * 128; i += blockDim.x) { WL[i >> 7][i & 127] = Wal[i]; WR[i >> 7][i & 127] = War[i]; }
    for (int i = tid; i < 2 * 128; i += blockDim.x) { WL[3 + (i >> 7)][i & 127] = Wsl[i]; WR[3 + (i >> 7)][i & 127] = Wsr[i]; }
    for (int i = tid; i < 3 * 128; i += blockDim.x) { WL[5 + (i >> 7)][i & 127] = Wel[i]; WR[5 + (i >> 7)][i & 127] = Wer[i]; }
    if (tid < 3) bias[tid] = ba[tid];
    if (tid < 2) bias[3 + tid] = bs[tid];
    if (tid >= 32 && tid < 35) bias[5 + (tid - 32)] = be[tid - 32];
    __syncthreads();

    const int lane = tid & 31;
    const int wid  = tid >> 5;
    const int node = blockIdx.x * (blockDim.x >> 5) + wid;
    if (node >= n) return;

    float iv = invd[node];
    float4 a = *reinterpret_cast<const float4*>(agg + (size_t)node * FEAT + lane * 4);
    a.x *= iv; a.y *= iv; a.z *= iv; a.w *= iv;
    float4 xv = *reinterpret_cast<const float4*>(h + (size_t)node * FEAT + lane * 4);

    float acc[8];
#pragma unroll
    for (int j = 0; j < 8; j++) {
        const float* wl = &WL[j][lane * 4];
        const float* wr = &WR[j][lane * 4];
        acc[j] = a.x * wl[0] + a.y * wl[1] + a.z * wl[2] + a.w * wl[3]
               + xv.x * wr[0] + xv.y * wr[1] + xv.z * wr[2] + xv.w * wr[3];
#pragma unroll
        for (int off = 16; off > 0; off >>= 1)
            acc[j] += __shfl_xor_sync(0xFFFFFFFF, acc[j], off);
    }

    if (lane == 0) {
        // layout: [N,3] age | [N,2] sex | [N,3] eth, concatenated
        out[(size_t)node * 3 + 0] = acc[0] + bias[0];
        out[(size_t)node * 3 + 1] = acc[1] + bias[1];
        out[(size_t)node * 3 + 2] = acc[2] + bias[2];
        float* sex = out + (size_t)n * 3;
        sex[(size_t)node * 2 + 0] = acc[3] + bias[3];
        sex[(size_t)node * 2 + 1] = acc[4] + bias[4];
        float* eth = out + (size_t)n * 5;
        eth[(size_t)node * 3 + 0] = acc[5] + bias[5];
        eth[(size_t)node * 3 + 1] = acc[6] + bias[6];
        eth[(size_t)node * 3 + 2] = acc[7] + bias[7];
    }
}

// ---------------- launch ----------------
extern "C" void kernel_launch(void* const* d_in, const int* in_sizes, int n_in,
                              void* d_out, int out_size) {
    const float* x  = (const float*)d_in[0];
    const int*   ei = (const int*)d_in[1];   // edge_index is int32 (JAX x64 disabled)
    const float *W1l = (const float*)d_in[2],  *W1r = (const float*)d_in[3],  *b1 = (const float*)d_in[4];
    const float *W2l = (const float*)d_in[5],  *W2r = (const float*)d_in[6],  *b2 = (const float*)d_in[7];
    const float *W3l = (const float*)d_in[8],  *W3r = (const float*)d_in[9],  *b3 = (const float*)d_in[10];
    const float *Wal = (const float*)d_in[11], *War = (const float*)d_in[12], *ba = (const float*)d_in[13];
    const float *Wsl = (const float*)d_in[14], *Wsr = (const float*)d_in[15], *bs = (const float*)d_in[16];
    const float *Wel = (const float*)d_in[17], *Wer = (const float*)d_in[18], *be = (const float*)d_in[19];
    float* out = (float*)d_out;

    const int N = in_sizes[0] / FEAT;
    const int E = in_sizes[1] / 2;
    const int* srcIdx = ei;
    const int* dstIdx = ei + E;

    float *agg, *bufA, *bufB, *deg, *invd;
    cudaGetSymbolAddress((void**)&agg,  g_agg);
    cudaGetSymbolAddress((void**)&bufA, g_bufA);
    cudaGetSymbolAddress((void**)&bufB, g_bufB);
    cudaGetSymbolAddress((void**)&deg,  g_deg);
    cudaGetSymbolAddress((void**)&invd, g_invd);

    const size_t featBytes = (size_t)N * FEAT * sizeof(float);

    const int gemmSmem = (2 * 128 * 128 + 2 * 32 * 128) * sizeof(float);  // 160 KB
    cudaFuncSetAttribute(sage_gemm_kernel, cudaFuncAttributeMaxDynamicSharedMemorySize, gemmSmem);

    // degree + inverse degree
    cudaMemsetAsync(deg, 0, (size_t)N * sizeof(float));
    deg_kernel<<<(E + 255) / 256, 256>>>(dstIdx, deg, E);
    invdeg_kernel<<<(N + 255) / 256, 256>>>(deg, invd, N);

    const int aggBlocks = (int)(((long long)E * 32 + 255) / 256);
    const int gemmBlocks = (N + 31) / 32;

    // layer 1: x -> bufA
    cudaMemsetAsync(agg, 0, featBytes);
    agg_kernel<<<aggBlocks, 256>>>(x, agg, srcIdx, dstIdx, E);
    sage_gemm_kernel<<<gemmBlocks, 256, gemmSmem>>>(agg, invd, x, W1l, W1r, b1, bufA, N, 1);

    // layer 2: bufA -> bufB
    cudaMemsetAsync(agg, 0, featBytes);
    agg_kernel<<<aggBlocks, 256>>>(bufA, agg, srcIdx, dstIdx, E);
    sage_gemm_kernel<<<gemmBlocks, 256, gemmSmem>>>(agg, invd, bufA, W2l, W2r, b2, bufB, N, 1);

    // layer 3: bufB -> bufA
    cudaMemsetAsync(agg, 0, featBytes);
    agg_kernel<<<aggBlocks, 256>>>(bufB, agg, srcIdx, dstIdx, E);
    sage_gemm_kernel<<<gemmBlocks, 256, gemmSmem>>>(agg, invd, bufB, W3l, W3r, b3, bufA, N, 1);

    // heads: aggregate bufA once, shared across the 3 heads
    cudaMemsetAsync(agg, 0, featBytes);
    agg_kernel<<<aggBlocks, 256>>>(bufA, agg, srcIdx, dstIdx, E);
    heads_kernel<<<(N + 7) / 8, 256>>>(agg, invd, bufA,
                                       Wal, War, ba, Wsl, Wsr, bs, Wel, Wer, be,
                                       out, N);
}

// round 3
// speedup vs baseline: 1.4320x; 1.4320x over previous
#include <cuda_runtime.h>
#include <cstdint>

#define NODES 100000
#define FEAT  128

// ---------------- scratch (static device memory; no allocation) ----------------
__device__ float g_agg [(size_t)NODES * FEAT];
__device__ float g_bufA[(size_t)NODES * FEAT];
__device__ float g_bufB[(size_t)NODES * FEAT];
__device__ float g_deg [NODES];
__device__ float g_invd[NODES];
__device__ float g_wt  [6 * 128 * 128];   // transposed W1l,W1r,W2l,W2r,W3l,W3r

// ---------------- degree ----------------
__global__ void deg_kernel(const int* __restrict__ dst, float* __restrict__ deg, int E) {
    int e = blockIdx.x * blockDim.x + threadIdx.x;
    if (e < E) atomicAdd(&deg[dst[e]], 1.0f);
}

__global__ void invdeg_kernel(const float* __restrict__ deg, float* __restrict__ invd, int n) {
    int i = blockIdx.x * blockDim.x + threadIdx.x;
    if (i < n) invd[i] = 1.0f / fmaxf(deg[i], 1.0f);
}

// ---------------- one-time weight transpose (6 matrices of 128x128) ----------------
__global__ void transpose6_kernel(const float* __restrict__ w0, const float* __restrict__ w1,
                                  const float* __restrict__ w2, const float* __restrict__ w3,
                                  const float* __restrict__ w4, const float* __restrict__ w5,
                                  float* __restrict__ outBase) {
    __shared__ float t[32][33];
    const float* in;
    switch (blockIdx.z) {
        case 0: in = w0; break; case 1: in = w1; break; case 2: in = w2; break;
        case 3: in = w3; break; case 4: in = w4; break; default: in = w5; break;
    }
    float* outp = outBase + (size_t)blockIdx.z * 16384;
    int tx = threadIdx.x, ty = threadIdx.y;        // 32 x 8
    int bx = blockIdx.x * 32, by = blockIdx.y * 32;
#pragma unroll
    for (int i = 0; i < 32; i += 8)
        t[ty + i][tx] = in[(by + ty + i) * 128 + bx + tx];
    __syncthreads();
#pragma unroll
    for (int i = 0; i < 32; i += 8)
        outp[(bx + ty + i) * 128 + by + tx] = t[tx][ty + i];
}

// ---------------- scatter-sum aggregation: warp per edge, float4 lanes ----------------
__global__ void agg_kernel(const float* __restrict__ feat, float* __restrict__ agg,
                           const int* __restrict__ srcIdx,
                           const int* __restrict__ dstIdx, int E) {
    int gtid = blockIdx.x * blockDim.x + threadIdx.x;
    int e    = gtid >> 5;
    int lane = gtid & 31;
    if (e >= E) return;
    int s = srcIdx[e];
    int d = dstIdx[e];
    const float4 v = *reinterpret_cast<const float4*>(feat + (size_t)s * FEAT + lane * 4);
    float* p = agg + (size_t)d * FEAT + lane * 4;
    asm volatile("red.global.add.v4.f32 [%0], {%1,%2,%3,%4};"
                 :: "l"(p), "f"(v.x), "f"(v.y), "f"(v.z), "f"(v.w)
                 : "memory");
}

// ---------------- fused SAGE layer GEMM ----------------
// out[row,j] = relu( (agg[row,:]*invd[row]) . WlT[:,j] + x[row,:] . WrT[:,j] + b[j] )
// WlT/WrT are PRE-TRANSPOSED [k][j].
// block: 256 threads, tile 64 rows x 128 cols. thread = 8 rows x 4 cols.
// warp = one row-group (8 rows) x 32 col-groups -> all a/xv smem reads are broadcasts.
__global__ __launch_bounds__(256) void sage_gemm_kernel(
        const float* __restrict__ agg, const float* __restrict__ invd,
        const float* __restrict__ x,
        const float* __restrict__ WlT, const float* __restrict__ WrT,
        const float* __restrict__ b,
        float* __restrict__ out, int n, int do_relu) {
    extern __shared__ float sm[];
    float* sWl = sm;               // 128*128 = 16384
    float* sWr = sm + 16384;       // 16384
    float* sA  = sm + 32768;       // 64*128 = 8192
    float* sX  = sm + 40960;       // 8192

    const int tid = threadIdx.x;

    // coalesced vectorized weight load (already transposed) -> conflict-free STS.128
    {
        const float4* wl4 = reinterpret_cast<const float4*>(WlT);
        const float4* wr4 = reinterpret_cast<const float4*>(WrT);
        float4* sWl4 = reinterpret_cast<float4*>(sWl);
        float4* sWr4 = reinterpret_cast<float4*>(sWr);
#pragma unroll
        for (int i = tid; i < 4096; i += 256) {
            sWl4[i] = wl4[i];
            sWr4[i] = wr4[i];
        }
    }

    const int row0 = blockIdx.x * 64;

    // stage 64 rows of agg (scaled by invd) and x
    for (int i = tid; i < 64 * 32; i += 256) {     // 64 rows * 32 float4
        int r = i >> 5, c4 = i & 31;
        int row = row0 + r;
        float4 a = make_float4(0.f, 0.f, 0.f, 0.f);
        float4 xv = make_float4(0.f, 0.f, 0.f, 0.f);
        if (row < n) {
            float iv = invd[row];
            a  = *reinterpret_cast<const float4*>(agg + (size_t)row * FEAT + c4 * 4);
            xv = *reinterpret_cast<const float4*>(x   + (size_t)row * FEAT + c4 * 4);
            a.x *= iv; a.y *= iv; a.z *= iv; a.w *= iv;
        }
        *reinterpret_cast<float4*>(sA + r * 128 + c4 * 4) = a;
        *reinterpret_cast<float4*>(sX + r * 128 + c4 * 4) = xv;
    }
    __syncthreads();

    const int cg = tid & 31;       // col group -> cols [cg*4, cg*4+4)
    const int rg = tid >> 5;       // warp id   -> rows [rg*8, rg*8+8)
    const int j0 = cg * 4;
    const int r0 = rg * 8;

    float acc[8][4];
#pragma unroll
    for (int r = 0; r < 8; r++)
#pragma unroll
        for (int c = 0; c < 4; c++) acc[r][c] = 0.0f;

    for (int k0 = 0; k0 < 128; k0 += 4) {
        float4 av[8], xvv[8];
#pragma unroll
        for (int r = 0; r < 8; r++) {
            av[r]  = *reinterpret_cast<const float4*>(sA + (r0 + r) * 128 + k0);
            xvv[r] = *reinterpret_cast<const float4*>(sX + (r0 + r) * 128 + k0);
        }
#pragma unroll
        for (int kk = 0; kk < 4; kk++) {
            float4 wl = *reinterpret_cast<const float4*>(sWl + (k0 + kk) * 128 + j0);
            float4 wr = *reinterpret_cast<const float4*>(sWr + (k0 + kk) * 128 + j0);
#pragma unroll
            for (int r = 0; r < 8; r++) {
                float a = reinterpret_cast<const float*>(&av[r])[kk];
                float v = reinterpret_cast<const float*>(&xvv[r])[kk];
                acc[r][0] += a * wl.x + v * wr.x;
                acc[r][1] += a * wl.y + v * wr.y;
                acc[r][2] += a * wl.z + v * wr.z;
                acc[r][3] += a * wl.w + v * wr.w;
            }
        }
    }

    float4 bv = *reinterpret_cast<const float4*>(b + j0);
#pragma unroll
    for (int r = 0; r < 8; r++) {
        int row = row0 + r0 + r;
        if (row < n) {
            float4 o;
            o.x = acc[r][0] + bv.x;
            o.y = acc[r][1] + bv.y;
            o.z = acc[r][2] + bv.z;
            o.w = acc[r][3] + bv.w;
            if (do_relu) {
                o.x = fmaxf(o.x, 0.0f); o.y = fmaxf(o.y, 0.0f);
                o.z = fmaxf(o.z, 0.0f); o.w = fmaxf(o.w, 0.0f);
            }
            *reinterpret_cast<float4*>(out + (size_t)row * FEAT + j0) = o;
        }
    }
}

// ---------------- heads: 8 output channels (age 3 | sex 2 | eth 3), warp per node ----------------
__global__ void heads_kernel(const float* __restrict__ agg, const float* __restrict__ invd,
                             const float* __restrict__ h,
                             const float* __restrict__ Wal, const float* __restrict__ War, const float* __restrict__ ba,
                             const float* __restrict__ Wsl, const float* __restrict__ Wsr, const float* __restrict__ bs,
                             const float* __restrict__ Wel, const float* __restrict__ Wer, const float* __restrict__ be,
                             float* __restrict__ out, int n) {
    __shared__ float WL[8][128];
    __shared__ float WR[8][128];
    __shared__ float bias[8];
    const int tid = threadIdx.x;

    for (int i = tid; i < 3 * 128; i += blockDim.x) { WL[i >> 7][i & 127] = Wal[i]; WR[i >> 7][i & 127] = War[i]; }
    for (int i = tid; i < 2 * 128; i += blockDim.x) { WL[3 + (i >> 7)][i & 127] = Wsl[i]; WR[3 + (i >> 7)][i & 127] = Wsr[i]; }
    for (int i = tid; i < 3 * 128; i += blockDim.x) { WL[5 + (i >> 7)][i & 127] = Wel[i]; WR[5 + (i >> 7)][i & 127] = Wer[i]; }
    if (tid < 3) bias[tid] = ba[tid];
    if (tid < 2) bias[3 + tid] = bs[tid];
    if (tid >= 32 && tid < 35) bias[5 + (tid - 32)] = be[tid - 32];
    __syncthreads();

    const int lane = tid & 31;
    const int wid  = tid >> 5;
    const int node = blockIdx.x * (blockDim.x >> 5) + wid;
    if (node >= n) return;

    float iv = invd[node];
    float4 a = *reinterpret_cast<const float4*>(agg + (size_t)node * FEAT + lane * 4);
    a.x *= iv; a.y *= iv; a.z *= iv; a.w *= iv;
    float4 xv = *reinterpret_cast<const float4*>(h + (size_t)node * FEAT + lane * 4);

    float acc[8];
#pragma unroll
    for (int j = 0; j < 8; j++) {
        const float* wl = &WL[j][lane * 4];
        const float* wr = &WR[j][lane * 4];
        acc[j] = a.x * wl[0] + a.y * wl[1] + a.z * wl[2] + a.w * wl[3]
               + xv.x * wr[0] + xv.y * wr[1] + xv.z * wr[2] + xv.w * wr[3];
#pragma unroll
        for (int off = 16; off > 0; off >>= 1)
            acc[j] += __shfl_xor_sync(0xFFFFFFFF, acc[j], off);
    }

    if (lane == 0) {
        out[(size_t)node * 3 + 0] = acc[0] + bias[0];
        out[(size_t)node * 3 + 1] = acc[1] + bias[1];
        out[(size_t)node * 3 + 2] = acc[2] + bias[2];
        float* sex = out + (size_t)n * 3;
        sex[(size_t)node * 2 + 0] = acc[3] + bias[3];
        sex[(size_t)node * 2 + 1] = acc[4] + bias[4];
        float* eth = out + (size_t)n * 5;
        eth[(size_t)node * 3 + 0] = acc[5] + bias[5];
        eth[(size_t)node * 3 + 1] = acc[6] + bias[6];
        eth[(size_t)node * 3 + 2] = acc[7] + bias[7];
    }
}

// ---------------- launch ----------------
extern "C" void kernel_launch(void* const* d_in, const int* in_sizes, int n_in,
                              void* d_out, int out_size) {
    const float* x  = (const float*)d_in[0];
    const int*   ei = (const int*)d_in[1];   // edge_index is int32 (JAX x64 disabled)
    const float *W1l = (const float*)d_in[2],  *W1r = (const float*)d_in[3],  *b1 = (const float*)d_in[4];
    const float *W2l = (const float*)d_in[5],  *W2r = (const float*)d_in[6],  *b2 = (const float*)d_in[7];
    const float *W3l = (const float*)d_in[8],  *W3r = (const float*)d_in[9],  *b3 = (const float*)d_in[10];
    const float *Wal = (const float*)d_in[11], *War = (const float*)d_in[12], *ba = (const float*)d_in[13];
    const float *Wsl = (const float*)d_in[14], *Wsr = (const float*)d_in[15], *bs = (const float*)d_in[16];
    const float *Wel = (const float*)d_in[17], *Wer = (const float*)d_in[18], *be = (const float*)d_in[19];
    float* out = (float*)d_out;

    const int N = in_sizes[0] / FEAT;
    const int E = in_sizes[1] / 2;
    const int* srcIdx = ei;
    const int* dstIdx = ei + E;

    float *agg, *bufA, *bufB, *deg, *invd, *wt;
    cudaGetSymbolAddress((void**)&agg,  g_agg);
    cudaGetSymbolAddress((void**)&bufA, g_bufA);
    cudaGetSymbolAddress((void**)&bufB, g_bufB);
    cudaGetSymbolAddress((void**)&deg,  g_deg);
    cudaGetSymbolAddress((void**)&invd, g_invd);
    cudaGetSymbolAddress((void**)&wt,   g_wt);

    const float* W1lT = wt;
    const float* W1rT = wt + 16384;
    const float* W2lT = wt + 32768;
    const float* W2rT = wt + 49152;
    const float* W3lT = wt + 65536;
    const float* W3rT = wt + 81920;

    const size_t featBytes = (size_t)N * FEAT * sizeof(float);

    const int gemmSmem = (2 * 128 * 128 + 2 * 64 * 128) * sizeof(float);  // 192 KB
    cudaFuncSetAttribute(sage_gemm_kernel, cudaFuncAttributeMaxDynamicSharedMemorySize, gemmSmem);

    // one-time weight transposes
    {
        dim3 g(4, 4, 6), blk(32, 8);
        transpose6_kernel<<<g, blk>>>(W1l, W1r, W2l, W2r, W3l, W3r, wt);
    }

    // degree + inverse degree
    cudaMemsetAsync(deg, 0, (size_t)N * sizeof(float));
    deg_kernel<<<(E + 255) / 256, 256>>>(dstIdx, deg, E);
    invdeg_kernel<<<(N + 255) / 256, 256>>>(deg, invd, N);

    const int aggBlocks = (int)(((long long)E * 32 + 255) / 256);
    const int gemmBlocks = (N + 63) / 64;

    // layer 1: x -> bufA
    cudaMemsetAsync(agg, 0, featBytes);
    agg_kernel<<<aggBlocks, 256>>>(x, agg, srcIdx, dstIdx, E);
    sage_gemm_kernel<<<gemmBlocks, 256, gemmSmem>>>(agg, invd, x, W1lT, W1rT, b1, bufA, N, 1);

    // layer 2: bufA -> bufB
    cudaMemsetAsync(agg, 0, featBytes);
    agg_kernel<<<aggBlocks, 256>>>(bufA, agg, srcIdx, dstIdx, E);
    sage_gemm_kernel<<<gemmBlocks, 256, gemmSmem>>>(agg, invd, bufA, W2lT, W2rT, b2, bufB, N, 1);

    // layer 3: bufB -> bufA
    cudaMemsetAsync(agg, 0, featBytes);
    agg_kernel<<<aggBlocks, 256>>>(bufB, agg, srcIdx, dstIdx, E);
    sage_gemm_kernel<<<gemmBlocks, 256, gemmSmem>>>(agg, invd, bufB, W3lT, W3rT, b3, bufA, N, 1);

    // heads: aggregate bufA once, shared across the 3 heads
    cudaMemsetAsync(agg, 0, featBytes);
    agg_kernel<<<aggBlocks, 256>>>(bufA, agg, srcIdx, dstIdx, E);
    heads_kernel<<<(N + 7) / 8, 256>>>(agg, invd, bufA,
                                       Wal, War, ba, Wsl, Wsr, bs, Wel, Wer, be,
                                       out, N);
}

// round 4
// speedup vs baseline: 2.7478x; 1.9188x over previous
#include <cuda_runtime.h>
#include <cstdint>

#define NODES 100000
#define EDGES 3200000
#define FEAT  128

// ---------------- scratch (static device memory; no allocation) ----------------
__device__ float g_agg [(size_t)NODES * FEAT];
__device__ float g_bufA[(size_t)NODES * FEAT];
__device__ float g_bufB[(size_t)NODES * FEAT];
__device__ float g_invd[NODES];
__device__ int   g_degi[NODES];
__device__ int   g_off [NODES + 1];
__device__ int   g_pos [NODES];
__device__ int   g_bsum[128];
__device__ int   g_csr [EDGES];
__device__ float g_wt  [6 * 128 * 128];   // transposed W1l,W1r,W2l,W2r,W3l,W3r

// ---------------- CSR build ----------------
__global__ void hist_kernel(const int* __restrict__ dst, int* __restrict__ degi, int E) {
    int e = blockIdx.x * blockDim.x + threadIdx.x;
    if (e < E) atomicAdd(&degi[dst[e]], 1);
}

// phase 1: per-block exclusive scan of 1024 elements
__global__ void scan1_kernel(const int* __restrict__ degi, int* __restrict__ off,
                             int* __restrict__ bsum, int n) {
    __shared__ int s[1024];
    int t = threadIdx.x;
    int i = blockIdx.x * 1024 + t;
    int v = (i < n) ? degi[i] : 0;
    s[t] = v;
    __syncthreads();
#pragma unroll
    for (int d = 1; d < 1024; d <<= 1) {
        int x = (t >= d) ? s[t - d] : 0;
        __syncthreads();
        s[t] += x;
        __syncthreads();
    }
    if (i < n) off[i] = s[t] - v;              // exclusive
    if (t == 1023) bsum[blockIdx.x] = s[t];    // block total
}

// phase 2: scan the block sums (single block, nb <= 128)
__global__ void scan2_kernel(int* __restrict__ bsum, int nb) {
    __shared__ int s[128];
    int t = threadIdx.x;
    int v = (t < nb) ? bsum[t] : 0;
    s[t] = v;
    __syncthreads();
#pragma unroll
    for (int d = 1; d < 128; d <<= 1) {
        int x = (t >= d) ? s[t - d] : 0;
        __syncthreads();
        s[t] += x;
        __syncthreads();
    }
    if (t < nb) bsum[t] = s[t] - v;            // exclusive
}

// phase 3: add block offsets, init fill cursors, inv degree, off[n]=E
__global__ void scan3_kernel(int* __restrict__ off, const int* __restrict__ bsum,
                             int* __restrict__ pos, const int* __restrict__ degi,
                             float* __restrict__ invd, int n, int E) {
    int i = blockIdx.x * blockDim.x + threadIdx.x;
    if (i < n) {
        int o = off[i] + bsum[i >> 10];
        off[i] = o;
        pos[i] = o;
        invd[i] = 1.0f / fmaxf((float)degi[i], 1.0f);
    }
    if (i == 0) off[n] = E;
}

__global__ void fill_kernel(const int* __restrict__ src, const int* __restrict__ dst,
                            int* __restrict__ pos, int* __restrict__ csr, int E) {
    int e = blockIdx.x * blockDim.x + threadIdx.x;
    if (e < E) {
        int d = dst[e];
        int p = atomicAdd(&pos[d], 1);
        csr[p] = src[e];
    }
}

// ---------------- gather-mean aggregation: warp per node ----------------
__global__ __launch_bounds__(256) void gather_kernel(
        const float* __restrict__ feat, float* __restrict__ agg,
        const int* __restrict__ csr, const int* __restrict__ off,
        const float* __restrict__ invd, int n) {
    int gtid = blockIdx.x * blockDim.x + threadIdx.x;
    int node = gtid >> 5;
    int lane = gtid & 31;
    if (node >= n) return;

    int beg = off[node];
    int end = off[node + 1];

    float4 acc0 = make_float4(0.f, 0.f, 0.f, 0.f);
    float4 acc1 = make_float4(0.f, 0.f, 0.f, 0.f);

    int j = beg;
    for (; j + 1 < end; j += 2) {
        int nb0 = __ldg(&csr[j]);
        int nb1 = __ldg(&csr[j + 1]);
        float4 v0 = *reinterpret_cast<const float4*>(feat + (size_t)nb0 * FEAT + lane * 4);
        float4 v1 = *reinterpret_cast<const float4*>(feat + (size_t)nb1 * FEAT + lane * 4);
        acc0.x += v0.x; acc0.y += v0.y; acc0.z += v0.z; acc0.w += v0.w;
        acc1.x += v1.x; acc1.y += v1.y; acc1.z += v1.z; acc1.w += v1.w;
    }
    if (j < end) {
        int nb = __ldg(&csr[j]);
        float4 v = *reinterpret_cast<const float4*>(feat + (size_t)nb * FEAT + lane * 4);
        acc0.x += v.x; acc0.y += v.y; acc0.z += v.z; acc0.w += v.w;
    }

    float iv = invd[node];
    float4 o;
    o.x = (acc0.x + acc1.x) * iv;
    o.y = (acc0.y + acc1.y) * iv;
    o.z = (acc0.z + acc1.z) * iv;
    o.w = (acc0.w + acc1.w) * iv;
    *reinterpret_cast<float4*>(agg + (size_t)node * FEAT + lane * 4) = o;
}

// ---------------- one-time weight transpose (6 matrices of 128x128) ----------------
__global__ void transpose6_kernel(const float* __restrict__ w0, const float* __restrict__ w1,
                                  const float* __restrict__ w2, const float* __restrict__ w3,
                                  const float* __restrict__ w4, const float* __restrict__ w5,
                                  float* __restrict__ outBase) {
    __shared__ float t[32][33];
    const float* in;
    switch (blockIdx.z) {
        case 0: in = w0; break; case 1: in = w1; break; case 2: in = w2; break;
        case 3: in = w3; break; case 4: in = w4; break; default: in = w5; break;
    }
    float* outp = outBase + (size_t)blockIdx.z * 16384;
    int tx = threadIdx.x, ty = threadIdx.y;        // 32 x 8
    int bx = blockIdx.x * 32, by = blockIdx.y * 32;
#pragma unroll
    for (int i = 0; i < 32; i += 8)
        t[ty + i][tx] = in[(by + ty + i) * 128 + bx + tx];
    __syncthreads();
#pragma unroll
    for (int i = 0; i < 32; i += 8)
        outp[(bx + ty + i) * 128 + by + tx] = t[tx][ty + i];
}

// ---------------- fused SAGE layer GEMM ----------------
// out[row,j] = relu( agg[row,:] . WlT[:,j] + x[row,:] . WrT[:,j] + b[j] )
// agg is already the MEAN. WlT/WrT pre-transposed [k][j].
// block: 256 threads, tile 64 rows x 128 cols. thread = 8 rows x 4 cols.
__global__ __launch_bounds__(256) void sage_gemm_kernel(
        const float* __restrict__ agg,
        const float* __restrict__ x,
        const float* __restrict__ WlT, const float* __restrict__ WrT,
        const float* __restrict__ b,
        float* __restrict__ out, int n, int do_relu) {
    extern __shared__ float sm[];
    float* sWl = sm;               // 16384
    float* sWr = sm + 16384;       // 16384
    float* sA  = sm + 32768;       // 8192
    float* sX  = sm + 40960;       // 8192

    const int tid = threadIdx.x;

    {
        const float4* wl4 = reinterpret_cast<const float4*>(WlT);
        const float4* wr4 = reinterpret_cast<const float4*>(WrT);
        float4* sWl4 = reinterpret_cast<float4*>(sWl);
        float4* sWr4 = reinterpret_cast<float4*>(sWr);
#pragma unroll
        for (int i = tid; i < 4096; i += 256) {
            sWl4[i] = wl4[i];
            sWr4[i] = wr4[i];
        }
    }

    const int row0 = blockIdx.x * 64;

    for (int i = tid; i < 64 * 32; i += 256) {
        int r = i >> 5, c4 = i & 31;
        int row = row0 + r;
        float4 a = make_float4(0.f, 0.f, 0.f, 0.f);
        float4 xv = make_float4(0.f, 0.f, 0.f, 0.f);
        if (row < n) {
            a  = *reinterpret_cast<const float4*>(agg + (size_t)row * FEAT + c4 * 4);
            xv = *reinterpret_cast<const float4*>(x   + (size_t)row * FEAT + c4 * 4);
        }
        *reinterpret_cast<float4*>(sA + r * 128 + c4 * 4) = a;
        *reinterpret_cast<float4*>(sX + r * 128 + c4 * 4) = xv;
    }
    __syncthreads();

    const int cg = tid & 31;
    const int rg = tid >> 5;
    const int j0 = cg * 4;
    const int r0 = rg * 8;

    float acc[8][4];
#pragma unroll
    for (int r = 0; r < 8; r++)
#pragma unroll
        for (int c = 0; c < 4; c++) acc[r][c] = 0.0f;

    for (int k0 = 0; k0 < 128; k0 += 4) {
        float4 av[8], xvv[8];
#pragma unroll
        for (int r = 0; r < 8; r++) {
            av[r]  = *reinterpret_cast<const float4*>(sA + (r0 + r) * 128 + k0);
            xvv[r] = *reinterpret_cast<const float4*>(sX + (r0 + r) * 128 + k0);
        }
#pragma unroll
        for (int kk = 0; kk < 4; kk++) {
            float4 wl = *reinterpret_cast<const float4*>(sWl + (k0 + kk) * 128 + j0);
            float4 wr = *reinterpret_cast<const float4*>(sWr + (k0 + kk) * 128 + j0);
#pragma unroll
            for (int r = 0; r < 8; r++) {
                float a = reinterpret_cast<const float*>(&av[r])[kk];
                float v = reinterpret_cast<const float*>(&xvv[r])[kk];
                acc[r][0] += a * wl.x + v * wr.x;
                acc[r][1] += a * wl.y + v * wr.y;
                acc[r][2] += a * wl.z + v * wr.z;
                acc[r][3] += a * wl.w + v * wr.w;
            }
        }
    }

    float4 bv = *reinterpret_cast<const float4*>(b + j0);
#pragma unroll
    for (int r = 0; r < 8; r++) {
        int row = row0 + r0 + r;
        if (row < n) {
            float4 o;
            o.x = acc[r][0] + bv.x;
            o.y = acc[r][1] + bv.y;
            o.z = acc[r][2] + bv.z;
            o.w = acc[r][3] + bv.w;
            if (do_relu) {
                o.x = fmaxf(o.x, 0.0f); o.y = fmaxf(o.y, 0.0f);
                o.z = fmaxf(o.z, 0.0f); o.w = fmaxf(o.w, 0.0f);
            }
            *reinterpret_cast<float4*>(out + (size_t)row * FEAT + j0) = o;
        }
    }
}

// ---------------- heads: 8 output channels (age 3 | sex 2 | eth 3), warp per node ----------------
__global__ void heads_kernel(const float* __restrict__ agg,
                             const float* __restrict__ h,
                             const float* __restrict__ Wal, const float* __restrict__ War, const float* __restrict__ ba,
                             const float* __restrict__ Wsl, const float* __restrict__ Wsr, const float* __restrict__ bs,
                             const float* __restrict__ Wel, const float* __restrict__ Wer, const float* __restrict__ be,
                             float* __restrict__ out, int n) {
    __shared__ float WL[8][128];
    __shared__ float WR[8][128];
    __shared__ float bias[8];
    const int tid = threadIdx.x;

    for (int i = tid; i < 3 * 128; i += blockDim.x) { WL[i >> 7][i & 127] = Wal[i]; WR[i >> 7][i & 127] = War[i]; }
    for (int i = tid; i < 2 * 128; i += blockDim.x) { WL[3 + (i >> 7)][i & 127] = Wsl[i]; WR[3 + (i >> 7)][i & 127] = Wsr[i]; }
    for (int i = tid; i < 3 * 128; i += blockDim.x) { WL[5 + (i >> 7)][i & 127] = Wel[i]; WR[5 + (i >> 7)][i & 127] = Wer[i]; }
    if (tid < 3) bias[tid] = ba[tid];
    if (tid < 2) bias[3 + tid] = bs[tid];
    if (tid >= 32 && tid < 35) bias[5 + (tid - 32)] = be[tid - 32];
    __syncthreads();

    const int lane = tid & 31;
    const int wid  = tid >> 5;
    const int node = blockIdx.x * (blockDim.x >> 5) + wid;
    if (node >= n) return;

    float4 a  = *reinterpret_cast<const float4*>(agg + (size_t)node * FEAT + lane * 4);
    float4 xv = *reinterpret_cast<const float4*>(h   + (size_t)node * FEAT + lane * 4);

    float acc[8];
#pragma unroll
    for (int j = 0; j < 8; j++) {
        const float* wl = &WL[j][lane * 4];
        const float* wr = &WR[j][lane * 4];
        acc[j] = a.x * wl[0] + a.y * wl[1] + a.z * wl[2] + a.w * wl[3]
               + xv.x * wr[0] + xv.y * wr[1] + xv.z * wr[2] + xv.w * wr[3];
#pragma unroll
        for (int off = 16; off > 0; off >>= 1)
            acc[j] += __shfl_xor_sync(0xFFFFFFFF, acc[j], off);
    }

    if (lane == 0) {
        out[(size_t)node * 3 + 0] = acc[0] + bias[0];
        out[(size_t)node * 3 + 1] = acc[1] + bias[1];
        out[(size_t)node * 3 + 2] = acc[2] + bias[2];
        float* sex = out + (size_t)n * 3;
        sex[(size_t)node * 2 + 0] = acc[3] + bias[3];
        sex[(size_t)node * 2 + 1] = acc[4] + bias[4];
        float* eth = out + (size_t)n * 5;
        eth[(size_t)node * 3 + 0] = acc[5] + bias[5];
        eth[(size_t)node * 3 + 1] = acc[6] + bias[6];
        eth[(size_t)node * 3 + 2] = acc[7] + bias[7];
    }
}

// ---------------- launch ----------------
extern "C" void kernel_launch(void* const* d_in, const int* in_sizes, int n_in,
                              void* d_out, int out_size) {
    const float* x  = (const float*)d_in[0];
    const int*   ei = (const int*)d_in[1];   // edge_index is int32
    const float *W1l = (const float*)d_in[2],  *W1r = (const float*)d_in[3],  *b1 = (const float*)d_in[4];
    const float *W2l = (const float*)d_in[5],  *W2r = (const float*)d_in[6],  *b2 = (const float*)d_in[7];
    const float *W3l = (const float*)d_in[8],  *W3r = (const float*)d_in[9],  *b3 = (const float*)d_in[10];
    const float *Wal = (const float*)d_in[11], *War = (const float*)d_in[12], *ba = (const float*)d_in[13];
    const float *Wsl = (const float*)d_in[14], *Wsr = (const float*)d_in[15], *bs = (const float*)d_in[16];
    const float *Wel = (const float*)d_in[17], *Wer = (const float*)d_in[18], *be = (const float*)d_in[19];
    float* out = (float*)d_out;

    const int N = in_sizes[0] / FEAT;
    const int E = in_sizes[1] / 2;
    const int* srcIdx = ei;
    const int* dstIdx = ei + E;

    float *agg, *bufA, *bufB, *invd, *wt;
    int *degi, *off, *pos, *bsum, *csr;
    cudaGetSymbolAddress((void**)&agg,  g_agg);
    cudaGetSymbolAddress((void**)&bufA, g_bufA);
    cudaGetSymbolAddress((void**)&bufB, g_bufB);
    cudaGetSymbolAddress((void**)&invd, g_invd);
    cudaGetSymbolAddress((void**)&degi, g_degi);
    cudaGetSymbolAddress((void**)&off,  g_off);
    cudaGetSymbolAddress((void**)&pos,  g_pos);
    cudaGetSymbolAddress((void**)&bsum, g_bsum);
    cudaGetSymbolAddress((void**)&csr,  g_csr);
    cudaGetSymbolAddress((void**)&wt,   g_wt);

    const float* W1lT = wt;
    const float* W1rT = wt + 16384;
    const float* W2lT = wt + 32768;
    const float* W2rT = wt + 49152;
    const float* W3lT = wt + 65536;
    const float* W3rT = wt + 81920;

    const int gemmSmem = (2 * 128 * 128 + 2 * 64 * 128) * sizeof(float);  // 192 KB
    cudaFuncSetAttribute(sage_gemm_kernel, cudaFuncAttributeMaxDynamicSharedMemorySize, gemmSmem);

    // one-time weight transposes
    {
        dim3 g(4, 4, 6), blk(32, 8);
        transpose6_kernel<<<g, blk>>>(W1l, W1r, W2l, W2r, W3l, W3r, wt);
    }

    // ---- CSR build ----
    const int nb = (N + 1023) / 1024;
    cudaMemsetAsync(degi, 0, (size_t)N * sizeof(int));
    hist_kernel<<<(E + 255) / 256, 256>>>(dstIdx, degi, E);
    scan1_kernel<<<nb, 1024>>>(degi, off, bsum, N);
    scan2_kernel<<<1, 128>>>(bsum, nb);
    scan3_kernel<<<(N + 255) / 256, 256>>>(off, bsum, pos, degi, invd, N, E);
    fill_kernel<<<(E + 255) / 256, 256>>>(srcIdx, dstIdx, pos, csr, E);

    const int gatherBlocks = (int)(((long long)N * 32 + 255) / 256);
    const int gemmBlocks = (N + 63) / 64;

    // layer 1: x -> bufA
    gather_kernel<<<gatherBlocks, 256>>>(x, agg, csr, off, invd, N);
    sage_gemm_kernel<<<gemmBlocks, 256, gemmSmem>>>(agg, x, W1lT, W1rT, b1, bufA, N, 1);

    // layer 2: bufA -> bufB
    gather_kernel<<<gatherBlocks, 256>>>(bufA, agg, csr, off, invd, N);
    sage_gemm_kernel<<<gemmBlocks, 256, gemmSmem>>>(agg, bufA, W2lT, W2rT, b2, bufB, N, 1);

    // layer 3: bufB -> bufA
    gather_kernel<<<gatherBlocks, 256>>>(bufB, agg, csr, off, invd, N);
    sage_gemm_kernel<<<gemmBlocks, 256, gemmSmem>>>(agg, bufB, W3lT, W3rT, b3, bufA, N, 1);

    // heads: aggregate bufA once, shared across the 3 heads
    gather_kernel<<<gatherBlocks, 256>>>(bufA, agg, csr, off, invd, N);
    heads_kernel<<<(N + 7) / 8, 256>>>(agg, bufA,
                                       Wal, War, ba, Wsl, Wsr, bs, Wel, Wer, be,
                                       out, N);
}

// round 6
// speedup vs baseline: 4.5460x; 1.6544x over previous
#include <cuda_runtime.h>
#include <cuda_bf16.h>
#include <cstdint>

#define NODES 100000
#define EDGES 3200000
#define FEAT  128

// ---------------- scratch (static device memory; no allocation) ----------------
__device__ float g_agg [(size_t)NODES * FEAT];
__device__ float g_bufA[(size_t)NODES * FEAT];
__device__ float g_bufB[(size_t)NODES * FEAT];
__device__ float g_invd[NODES];
__device__ int   g_degi[NODES];
__device__ int   g_off [NODES + 1];
__device__ int   g_pos [NODES];
__device__ int   g_bsum[128];
__device__ int   g_csr [EDGES];
__device__ float g_yl  [(size_t)NODES * 8];
__device__ float g_yr  [(size_t)NODES * 8];

// ================= helpers =================
__device__ __forceinline__ uint32_t smem_u32(const void* p) {
    uint32_t a;
    asm("{ .reg .u64 t; cvta.to.shared.u64 t, %1; cvt.u32.u64 %0, t; }" : "=r"(a) : "l"(p));
    return a;
}

__device__ __forceinline__ uint32_t pack_bf16x2(float a, float b) {
    __nv_bfloat162 h = __floats2bfloat162_rn(a, b);
    return reinterpret_cast<uint32_t&>(h);
}

__device__ __forceinline__ void ldsm_x4(uint32_t (&r)[4], uint32_t addr) {
    asm volatile("ldmatrix.sync.aligned.m8n8.x4.shared.b16 {%0,%1,%2,%3}, [%4];"
                 : "=r"(r[0]), "=r"(r[1]), "=r"(r[2]), "=r"(r[3]) : "r"(addr));
}

__device__ __forceinline__ void mma_bf16(float (&d)[4], const uint32_t (&a)[4],
                                         uint32_t b0, uint32_t b1) {
    asm volatile("mma.sync.aligned.m16n8k16.row.col.f32.bf16.bf16.f32 "
                 "{%0,%1,%2,%3}, {%4,%5,%6,%7}, {%8,%9}, {%0,%1,%2,%3};"
                 : "+f"(d[0]), "+f"(d[1]), "+f"(d[2]), "+f"(d[3])
                 : "r"(a[0]), "r"(a[1]), "r"(a[2]), "r"(a[3]), "r"(b0), "r"(b1));
}

// ---------------- CSR build ----------------
__global__ void hist_kernel(const int* __restrict__ dst, int* __restrict__ degi, int E) {
    int e = blockIdx.x * blockDim.x + threadIdx.x;
    if (e < E) atomicAdd(&degi[dst[e]], 1);
}

__global__ void scan1_kernel(const int* __restrict__ degi, int* __restrict__ off,
                             int* __restrict__ bsum, int n) {
    __shared__ int s[1024];
    int t = threadIdx.x;
    int i = blockIdx.x * 1024 + t;
    int v = (i < n) ? degi[i] : 0;
    s[t] = v;
    __syncthreads();
#pragma unroll
    for (int d = 1; d < 1024; d <<= 1) {
        int x = (t >= d) ? s[t - d] : 0;
        __syncthreads();
        s[t] += x;
        __syncthreads();
    }
    if (i < n) off[i] = s[t] - v;
    if (t == 1023) bsum[blockIdx.x] = s[t];
}

__global__ void scan2_kernel(int* __restrict__ bsum, int nb) {
    __shared__ int s[128];
    int t = threadIdx.x;
    int v = (t < nb) ? bsum[t] : 0;
    s[t] = v;
    __syncthreads();
#pragma unroll
    for (int d = 1; d < 128; d <<= 1) {
        int x = (t >= d) ? s[t - d] : 0;
        __syncthreads();
        s[t] += x;
        __syncthreads();
    }
    if (t < nb) bsum[t] = s[t] - v;
}

__global__ void scan3_kernel(int* __restrict__ off, const int* __restrict__ bsum,
                             int* __restrict__ pos, const int* __restrict__ degi,
                             float* __restrict__ invd, int n, int E) {
    int i = blockIdx.x * blockDim.x + threadIdx.x;
    if (i < n) {
        int o = off[i] + bsum[i >> 10];
        off[i] = o;
        pos[i] = o;
        invd[i] = 1.0f / fmaxf((float)degi[i], 1.0f);
    }
    if (i == 0) off[n] = E;
}

__global__ void fill_kernel(const int* __restrict__ src, const int* __restrict__ dst,
                            int* __restrict__ pos, int* __restrict__ csr, int E) {
    int e = blockIdx.x * blockDim.x + threadIdx.x;
    if (e < E) {
        int d = dst[e];
        int p = atomicAdd(&pos[d], 1);
        csr[p] = src[e];
    }
}

// ---------------- gather-mean aggregation: warp per node (fp32, 128 feats) ----------------
__global__ __launch_bounds__(256) void gather_kernel(
        const float* __restrict__ feat, float* __restrict__ agg,
        const int* __restrict__ csr, const int* __restrict__ off,
        const float* __restrict__ invd, int n) {
    int gtid = blockIdx.x * blockDim.x + threadIdx.x;
    int node = gtid >> 5;
    int lane = gtid & 31;
    if (node >= n) return;

    int beg = off[node];
    int end = off[node + 1];

    float4 acc0 = make_float4(0.f, 0.f, 0.f, 0.f);
    float4 acc1 = make_float4(0.f, 0.f, 0.f, 0.f);

    int j = beg;
    for (; j + 1 < end; j += 2) {
        int nb0 = __ldg(&csr[j]);
        int nb1 = __ldg(&csr[j + 1]);
        float4 v0 = *reinterpret_cast<const float4*>(feat + (size_t)nb0 * FEAT + lane * 4);
        float4 v1 = *reinterpret_cast<const float4*>(feat + (size_t)nb1 * FEAT + lane * 4);
        acc0.x += v0.x; acc0.y += v0.y; acc0.z += v0.z; acc0.w += v0.w;
        acc1.x += v1.x; acc1.y += v1.y; acc1.z += v1.z; acc1.w += v1.w;
    }
    if (j < end) {
        int nb = __ldg(&csr[j]);
        float4 v = *reinterpret_cast<const float4*>(feat + (size_t)nb * FEAT + lane * 4);
        acc0.x += v.x; acc0.y += v.y; acc0.z += v.z; acc0.w += v.w;
    }

    float iv = invd[node];
    float4 o;
    o.x = (acc0.x + acc1.x) * iv;
    o.y = (acc0.y + acc1.y) * iv;
    o.z = (acc0.z + acc1.z) * iv;
    o.w = (acc0.w + acc1.w) * iv;
    *reinterpret_cast<float4*>(agg + (size_t)node * FEAT + lane * 4) = o;
}

// ---------------- mma.sync SAGE GEMM (bf16 3-chain split, fp32 accum) ----------------
// out[row,j] = relu( agg[row,:] . Wl[j,:] + x[row,:] . Wr[j,:] + b[j] )
// CTA tile 128 rows x 128 cols; 2 phases (agg*Wl, x*Wr) accumulate into register frags.
// smem per phase: A_hi/A_lo [128m][128k] bf16, B_hi/B_lo [128n][128k] bf16, pitch 272B.
#define PITCHB 272
#define SM_AH  0
#define SM_AL  34816
#define SM_BH  69632
#define SM_BL  104448
#define SM_TOT_MMA 139264

__global__ __launch_bounds__(256, 1) void sage_gemm_mma(
        const float* __restrict__ agg, const float* __restrict__ x,
        const float* __restrict__ Wl, const float* __restrict__ Wr,
        const float* __restrict__ b, float* __restrict__ out, int n) {
    extern __shared__ char smem[];
    const uint32_t sbase = smem_u32(smem);
    const int tid  = threadIdx.x;
    const int wid  = tid >> 5;
    const int lane = tid & 31;
    const int wr   = wid & 3;      // warp row group: rows [wr*32, wr*32+32)
    const int wc   = wid >> 2;     // warp col group: cols [wc*64, wc*64+64)
    const int grp  = lane >> 2;
    const int tig  = lane & 3;
    const int t8   = lane >> 3;
    const int rr   = lane & 7;
    const int row0 = blockIdx.x * 128;

    // per-lane ldmatrix address components
    const int a_row_part = (t8 & 1) * 8 + rr;          // within 16-row tile
    const uint32_t a_koff = (uint32_t)((t8 >> 1) * 16); // bytes
    const int b_row_part = (t8 >> 1) * 8 + rr;
    const uint32_t b_koff = (uint32_t)((t8 & 1) * 16);

    float D[2][8][4];
#pragma unroll
    for (int mt = 0; mt < 2; mt++)
#pragma unroll
        for (int nt = 0; nt < 8; nt++)
#pragma unroll
            for (int k = 0; k < 4; k++) D[mt][nt][k] = 0.0f;

#pragma unroll
    for (int phase = 0; phase < 2; phase++) {
        const float* Asrc = phase ? x  : agg;
        const float* Bsrc = phase ? Wr : Wl;

        __syncthreads();   // prior phase's reads complete before restage

        // stage A rows (zero-pad past n), split bf16 hi/lo
        for (int i = tid; i < 128 * 32; i += 256) {
            int r = i >> 5, g = i & 31;
            float4 v = make_float4(0.f, 0.f, 0.f, 0.f);
            int row = row0 + r;
            if (row < n) v = *reinterpret_cast<const float4*>(Asrc + (size_t)row * FEAT + g * 4);
            float hx = __bfloat162float(__float2bfloat16_rn(v.x));
            float hy = __bfloat162float(__float2bfloat16_rn(v.y));
            float hz = __bfloat162float(__float2bfloat16_rn(v.z));
            float hw = __bfloat162float(__float2bfloat16_rn(v.w));
            uint2 hi2 = make_uint2(pack_bf16x2(v.x, v.y), pack_bf16x2(v.z, v.w));
            uint2 lo2 = make_uint2(pack_bf16x2(v.x - hx, v.y - hy),
                                   pack_bf16x2(v.z - hz, v.w - hw));
            uint32_t off = (uint32_t)(r * PITCHB + g * 8);
            *reinterpret_cast<uint2*>(smem + SM_AH + off) = hi2;
            *reinterpret_cast<uint2*>(smem + SM_AL + off) = lo2;
        }
        // stage B = weights [n=j][k], split hi/lo
        for (int i = tid; i < 128 * 32; i += 256) {
            int j = i >> 5, g = i & 31;
            float4 v = *reinterpret_cast<const float4*>(Bsrc + (size_t)j * FEAT + g * 4);
            float hx = __bfloat162float(__float2bfloat16_rn(v.x));
            float hy = __bfloat162float(__float2bfloat16_rn(v.y));
            float hz = __bfloat162float(__float2bfloat16_rn(v.z));
            float hw = __bfloat162float(__float2bfloat16_rn(v.w));
            uint2 hi2 = make_uint2(pack_bf16x2(v.x, v.y), pack_bf16x2(v.z, v.w));
            uint2 lo2 = make_uint2(pack_bf16x2(v.x - hx, v.y - hy),
                                   pack_bf16x2(v.z - hz, v.w - hw));
            uint32_t off = (uint32_t)(j * PITCHB + g * 8);
            *reinterpret_cast<uint2*>(smem + SM_BH + off) = hi2;
            *reinterpret_cast<uint2*>(smem + SM_BL + off) = lo2;
        }
        __syncthreads();

#pragma unroll
        for (int ks = 0; ks < 8; ks++) {
            const uint32_t k0b = (uint32_t)(ks * 32);   // 16 k * 2 bytes

            uint32_t ahi[2][4], alo[2][4];
#pragma unroll
            for (int mt = 0; mt < 2; mt++) {
                uint32_t addr = sbase + SM_AH
                              + (uint32_t)((wr * 32 + mt * 16 + a_row_part) * PITCHB)
                              + k0b + a_koff;
                ldsm_x4(ahi[mt], addr);
                ldsm_x4(alo[mt], addr + (SM_AL - SM_AH));
            }

            uint32_t bhi[8][2], blo[8][2];
#pragma unroll
            for (int nq = 0; nq < 4; nq++) {
                uint32_t addr = sbase + SM_BH
                              + (uint32_t)((wc * 64 + nq * 16 + b_row_part) * PITCHB)
                              + k0b + b_koff;
                uint32_t r4[4];
                ldsm_x4(r4, addr);
                bhi[nq * 2][0] = r4[0]; bhi[nq * 2][1] = r4[1];
                bhi[nq * 2 + 1][0] = r4[2]; bhi[nq * 2 + 1][1] = r4[3];
                ldsm_x4(r4, addr + (SM_BL - SM_BH));
                blo[nq * 2][0] = r4[0]; blo[nq * 2][1] = r4[1];
                blo[nq * 2 + 1][0] = r4[2]; blo[nq * 2 + 1][1] = r4[3];
            }

#pragma unroll
            for (int mt = 0; mt < 2; mt++)
#pragma unroll
                for (int nt = 0; nt < 8; nt++) {
                    mma_bf16(D[mt][nt], ahi[mt], bhi[nt][0], bhi[nt][1]);  // hi*hi
                    mma_bf16(D[mt][nt], ahi[mt], blo[nt][0], blo[nt][1]);  // hi*lo
                    mma_bf16(D[mt][nt], alo[mt], bhi[nt][0], bhi[nt][1]);  // lo*hi
                }
        }
    }

    // epilogue: bias + relu, direct float2 stores
#pragma unroll
    for (int mt = 0; mt < 2; mt++) {
        int row_lo = row0 + wr * 32 + mt * 16 + grp;
        int row_hi = row_lo + 8;
#pragma unroll
        for (int nt = 0; nt < 8; nt++) {
            int c0 = wc * 64 + nt * 8 + tig * 2;
            float bx = __ldg(b + c0);
            float by = __ldg(b + c0 + 1);
            if (row_lo < n) {
                float2 o;
                o.x = fmaxf(D[mt][nt][0] + bx, 0.0f);
                o.y = fmaxf(D[mt][nt][1] + by, 0.0f);
                *reinterpret_cast<float2*>(out + (size_t)row_lo * FEAT + c0) = o;
            }
            if (row_hi < n) {
                float2 o;
                o.x = fmaxf(D[mt][nt][2] + bx, 0.0f);
                o.y = fmaxf(D[mt][nt][3] + by, 0.0f);
                *reinterpret_cast<float2*>(out + (size_t)row_hi * FEAT + c0) = o;
            }
        }
    }
}

// ---------------- head projection: y = h @ W^T for 8 output channels, warp per node ----------------
__global__ void project_kernel(const float* __restrict__ h,
                               const float* __restrict__ Wal, const float* __restrict__ War, const float* __restrict__ ba,
                               const float* __restrict__ Wsl, const float* __restrict__ Wsr, const float* __restrict__ bs,
                               const float* __restrict__ Wel, const float* __restrict__ Wer, const float* __restrict__ be,
                               float* __restrict__ yl, float* __restrict__ yr, int n) {
    __shared__ float WL[8][128];
    __shared__ float WR[8][128];
    __shared__ float bias[8];
    const int tid = threadIdx.x;

    for (int i = tid; i < 3 * 128; i += blockDim.x) { WL[i >> 7][i & 127] = Wal[i]; WR[i >> 7][i & 127] = War[i]; }
    for (int i = tid; i < 2 * 128; i += blockDim.x) { WL[3 + (i >> 7)][i & 127] = Wsl[i]; WR[3 + (i >> 7)][i & 127] = Wsr[i]; }
    for (int i = tid; i < 3 * 128; i += blockDim.x) { WL[5 + (i >> 7)][i & 127] = Wel[i]; WR[5 + (i >> 7)][i & 127] = Wer[i]; }
    if (tid < 3) bias[tid] = ba[tid];
    if (tid < 2) bias[3 + tid] = bs[tid];
    if (tid >= 32 && tid < 35) bias[5 + (tid - 32)] = be[tid - 32];
    __syncthreads();

    const int lane = tid & 31;
    const int wid  = tid >> 5;
    const int node = blockIdx.x * (blockDim.x >> 5) + wid;
    if (node >= n) return;

    float4 xv = *reinterpret_cast<const float4*>(h + (size_t)node * FEAT + lane * 4);

    float accl[8], accr[8];
#pragma unroll
    for (int j = 0; j < 8; j++) {
        const float* wl = &WL[j][lane * 4];
        const float* wr = &WR[j][lane * 4];
        accl[j] = xv.x * wl[0] + xv.y * wl[1] + xv.z * wl[2] + xv.w * wl[3];
        accr[j] = xv.x * wr[0] + xv.y * wr[1] + xv.z * wr[2] + xv.w * wr[3];
#pragma unroll
        for (int off = 16; off > 0; off >>= 1) {
            accl[j] += __shfl_xor_sync(0xFFFFFFFF, accl[j], off);
            accr[j] += __shfl_xor_sync(0xFFFFFFFF, accr[j], off);
        }
    }

    if (lane == 0) {
#pragma unroll
        for (int j = 0; j < 8; j++) {
            yl[(size_t)node * 8 + j] = accl[j];
            yr[(size_t)node * 8 + j] = accr[j] + bias[j];
        }
    }
}

// ---------------- head gather: thread per node, 8-dim mean + root term ----------------
__global__ __launch_bounds__(256) void head_gather_kernel(
        const float* __restrict__ yl, const float* __restrict__ yr,
        const int* __restrict__ csr, const int* __restrict__ off,
        const float* __restrict__ invd, float* __restrict__ out, int n) {
    int node = blockIdx.x * blockDim.x + threadIdx.x;
    if (node >= n) return;

    int beg = off[node];
    int end = off[node + 1];

    float4 s0 = make_float4(0.f, 0.f, 0.f, 0.f);
    float4 s1 = make_float4(0.f, 0.f, 0.f, 0.f);
    for (int e = beg; e < end; e++) {
        int s = __ldg(&csr[e]);
        const float4* p = reinterpret_cast<const float4*>(yl + (size_t)s * 8);
        float4 v0 = p[0], v1 = p[1];
        s0.x += v0.x; s0.y += v0.y; s0.z += v0.z; s0.w += v0.w;
        s1.x += v1.x; s1.y += v1.y; s1.z += v1.z; s1.w += v1.w;
    }

    float iv = invd[node];
    const float4* rp = reinterpret_cast<const float4*>(yr + (size_t)node * 8);
    float4 r0 = rp[0], r1 = rp[1];
    float o0 = s0.x * iv + r0.x;
    float o1 = s0.y * iv + r0.y;
    float o2 = s0.z * iv + r0.z;
    float o3 = s0.w * iv + r0.w;
    float o4 = s1.x * iv + r1.x;
    float o5 = s1.y * iv + r1.y;
    float o6 = s1.z * iv + r1.z;
    float o7 = s1.w * iv + r1.w;

    // layout: [N,3] age | [N,2] sex | [N,3] eth
    out[(size_t)node * 3 + 0] = o0;
    out[(size_t)node * 3 + 1] = o1;
    out[(size_t)node * 3 + 2] = o2;
    float* sex = out + (size_t)n * 3;
    sex[(size_t)node * 2 + 0] = o3;
    sex[(size_t)node * 2 + 1] = o4;
    float* eth = out + (size_t)n * 5;
    eth[(size_t)node * 3 + 0] = o5;
    eth[(size_t)node * 3 + 1] = o6;
    eth[(size_t)node * 3 + 2] = o7;
}

// ---------------- launch ----------------
extern "C" void kernel_launch(void* const* d_in, const int* in_sizes, int n_in,
                              void* d_out, int out_size) {
    const float* x  = (const float*)d_in[0];
    const int*   ei = (const int*)d_in[1];
    const float *W1l = (const float*)d_in[2],  *W1r = (const float*)d_in[3],  *b1 = (const float*)d_in[4];
    const float *W2l = (const float*)d_in[5],  *W2r = (const float*)d_in[6],  *b2 = (const float*)d_in[7];
    const float *W3l = (const float*)d_in[8],  *W3r = (const float*)d_in[9],  *b3 = (const float*)d_in[10];
    const float *Wal = (const float*)d_in[11], *War = (const float*)d_in[12], *ba = (const float*)d_in[13];
    const float *Wsl = (const float*)d_in[14], *Wsr = (const float*)d_in[15], *bs = (const float*)d_in[16];
    const float *Wel = (const float*)d_in[17], *Wer = (const float*)d_in[18], *be = (const float*)d_in[19];
    float* out = (float*)d_out;

    const int N = in_sizes[0] / FEAT;
    const int E = in_sizes[1] / 2;
    const int* srcIdx = ei;
    const int* dstIdx = ei + E;

    float *agg, *bufA, *bufB, *invd, *yl, *yr;
    int *degi, *off, *pos, *bsum, *csr;
    cudaGetSymbolAddress((void**)&agg,  g_agg);
    cudaGetSymbolAddress((void**)&bufA, g_bufA);
    cudaGetSymbolAddress((void**)&bufB, g_bufB);
    cudaGetSymbolAddress((void**)&invd, g_invd);
    cudaGetSymbolAddress((void**)&degi, g_degi);
    cudaGetSymbolAddress((void**)&off,  g_off);
    cudaGetSymbolAddress((void**)&pos,  g_pos);
    cudaGetSymbolAddress((void**)&bsum, g_bsum);
    cudaGetSymbolAddress((void**)&csr,  g_csr);
    cudaGetSymbolAddress((void**)&yl,   g_yl);
    cudaGetSymbolAddress((void**)&yr,   g_yr);

    cudaFuncSetAttribute(sage_gemm_mma, cudaFuncAttributeMaxDynamicSharedMemorySize, SM_TOT_MMA);

    // ---- CSR build ----
    const int nb = (N + 1023) / 1024;
    cudaMemsetAsync(degi, 0, (size_t)N * sizeof(int));
    hist_kernel<<<(E + 255) / 256, 256>>>(dstIdx, degi, E);
    scan1_kernel<<<nb, 1024>>>(degi, off, bsum, N);
    scan2_kernel<<<1, 128>>>(bsum, nb);
    scan3_kernel<<<(N + 255) / 256, 256>>>(off, bsum, pos, degi, invd, N, E);
    fill_kernel<<<(E + 255) / 256, 256>>>(srcIdx, dstIdx, pos, csr, E);

    const int gatherBlocks = (int)(((long long)N * 32 + 255) / 256);
    const int gemmBlocks = (N + 127) / 128;

    // layer 1: x -> bufA
    gather_kernel<<<gatherBlocks, 256>>>(x, agg, csr, off, invd, N);
    sage_gemm_mma<<<gemmBlocks, 256, SM_TOT_MMA>>>(agg, x, W1l, W1r, b1, bufA, N);

    // layer 2: bufA -> bufB
    gather_kernel<<<gatherBlocks, 256>>>(bufA, agg, csr, off, invd, N);
    sage_gemm_mma<<<gemmBlocks, 256, SM_TOT_MMA>>>(agg, bufA, W2l, W2r, b2, bufB, N);

    // layer 3: bufB -> bufA
    gather_kernel<<<gatherBlocks, 256>>>(bufB, agg, csr, off, invd, N);
    sage_gemm_mma<<<gemmBlocks, 256, SM_TOT_MMA>>>(agg, bufB, W3l, W3r, b3, bufA, N);

    // heads: project h3 to 8 dims, then 8-dim gather-mean
    project_kernel<<<(N + 7) / 8, 256>>>(bufA, Wal, War, ba, Wsl, Wsr, bs, Wel, Wer, be,
                                         yl, yr, N);
    head_gather_kernel<<<(N + 255) / 256, 256>>>(yl, yr, csr, off, invd, out, N);
}

// round 7
// speedup vs baseline: 4.9770x; 1.0948x over previous
#include <cuda_runtime.h>
#include <cuda_bf16.h>
#include <cuda_fp16.h>
#include <cstdint>

#define NODES 100000
#define EDGES 3200000
#define FEAT  128

// ---------------- scratch (static device memory; no allocation) ----------------
__device__ float  g_agg [(size_t)NODES * FEAT];
__device__ __half g_x16 [(size_t)NODES * FEAT];
__device__ __half g_h16A[(size_t)NODES * FEAT];
__device__ __half g_h16B[(size_t)NODES * FEAT];
__device__ float  g_invd[NODES];
__device__ int    g_degi[NODES];
__device__ int    g_off [NODES + 1];
__device__ int    g_pos [NODES];
__device__ int    g_bsum[128];
__device__ int    g_csr [EDGES];
__device__ float  g_yl  [(size_t)NODES * 8];
__device__ float  g_yr  [(size_t)NODES * 8];

// ================= helpers =================
__device__ __forceinline__ uint32_t smem_u32(const void* p) {
    uint32_t a;
    asm("{ .reg .u64 t; cvta.to.shared.u64 t, %1; cvt.u32.u64 %0, t; }" : "=r"(a) : "l"(p));
    return a;
}

__device__ __forceinline__ uint32_t pack_bf16x2(float a, float b) {
    __nv_bfloat162 h = __floats2bfloat162_rn(a, b);
    return reinterpret_cast<uint32_t&>(h);
}

__device__ __forceinline__ void ldsm_x4(uint32_t (&r)[4], uint32_t addr) {
    asm volatile("ldmatrix.sync.aligned.m8n8.x4.shared.b16 {%0,%1,%2,%3}, [%4];"
                 : "=r"(r[0]), "=r"(r[1]), "=r"(r[2]), "=r"(r[3]) : "r"(addr));
}

__device__ __forceinline__ void mma_bf16(float (&d)[4], const uint32_t (&a)[4],
                                         uint32_t b0, uint32_t b1) {
    asm volatile("mma.sync.aligned.m16n8k16.row.col.f32.bf16.bf16.f32 "
                 "{%0,%1,%2,%3}, {%4,%5,%6,%7}, {%8,%9}, {%0,%1,%2,%3};"
                 : "+f"(d[0]), "+f"(d[1]), "+f"(d[2]), "+f"(d[3])
                 : "r"(a[0]), "r"(a[1]), "r"(a[2]), "r"(a[3]), "r"(b0), "r"(b1));
}

__device__ __forceinline__ float4 load_h4_as_f4(const __half* p) {
    uint2 u = *reinterpret_cast<const uint2*>(p);
    float2 a = __half22float2(reinterpret_cast<__half2&>(u.x));
    float2 b = __half22float2(reinterpret_cast<__half2&>(u.y));
    return make_float4(a.x, a.y, b.x, b.y);
}

// ---------------- fp32 -> fp16 convert ----------------
__global__ void cvt16_kernel(const float* __restrict__ in, __half* __restrict__ out, int n4) {
    int i = blockIdx.x * blockDim.x + threadIdx.x;
    if (i < n4) {
        float4 v = reinterpret_cast<const float4*>(in)[i];
        __half2 h0 = __floats2half2_rn(v.x, v.y);
        __half2 h1 = __floats2half2_rn(v.z, v.w);
        uint2 o = make_uint2(reinterpret_cast<uint32_t&>(h0), reinterpret_cast<uint32_t&>(h1));
        reinterpret_cast<uint2*>(out)[i] = o;
    }
}

// ---------------- CSR build ----------------
__global__ void hist_kernel(const int* __restrict__ dst, int* __restrict__ degi, int E) {
    int e = blockIdx.x * blockDim.x + threadIdx.x;
    if (e < E) atomicAdd(&degi[dst[e]], 1);
}

__global__ void scan1_kernel(const int* __restrict__ degi, int* __restrict__ off,
                             int* __restrict__ bsum, int n) {
    __shared__ int s[1024];
    int t = threadIdx.x;
    int i = blockIdx.x * 1024 + t;
    int v = (i < n) ? degi[i] : 0;
    s[t] = v;
    __syncthreads();
#pragma unroll
    for (int d = 1; d < 1024; d <<= 1) {
        int x = (t >= d) ? s[t - d] : 0;
        __syncthreads();
        s[t] += x;
        __syncthreads();
    }
    if (i < n) off[i] = s[t] - v;
    if (t == 1023) bsum[blockIdx.x] = s[t];
}

__global__ void scan2_kernel(int* __restrict__ bsum, int nb) {
    __shared__ int s[128];
    int t = threadIdx.x;
    int v = (t < nb) ? bsum[t] : 0;
    s[t] = v;
    __syncthreads();
#pragma unroll
    for (int d = 1; d < 128; d <<= 1) {
        int x = (t >= d) ? s[t - d] : 0;
        __syncthreads();
        s[t] += x;
        __syncthreads();
    }
    if (t < nb) bsum[t] = s[t] - v;
}

__global__ void scan3_kernel(int* __restrict__ off, const int* __restrict__ bsum,
                             int* __restrict__ pos, const int* __restrict__ degi,
                             float* __restrict__ invd, int n, int E) {
    int i = blockIdx.x * blockDim.x + threadIdx.x;
    if (i < n) {
        int o = off[i] + bsum[i >> 10];
        off[i] = o;
        pos[i] = o;
        invd[i] = 1.0f / fmaxf((float)degi[i], 1.0f);
    }
    if (i == 0) off[n] = E;
}

__global__ void fill_kernel(const int* __restrict__ src, const int* __restrict__ dst,
                            int* __restrict__ pos, int* __restrict__ csr, int E) {
    int e = blockIdx.x * blockDim.x + threadIdx.x;
    if (e < E) {
        int d = dst[e];
        int p = atomicAdd(&pos[d], 1);
        csr[p] = src[e];
    }
}

// ---------------- gather-mean aggregation: warp per node, fp16 feats -> fp32 agg ----------------
__global__ __launch_bounds__(256) void gather16_kernel(
        const __half* __restrict__ feat, float* __restrict__ agg,
        const int* __restrict__ csr, const int* __restrict__ off,
        const float* __restrict__ invd, int n) {
    int gtid = blockIdx.x * blockDim.x + threadIdx.x;
    int node = gtid >> 5;
    int lane = gtid & 31;
    if (node >= n) return;

    int beg = off[node];
    int end = off[node + 1];

    float4 acc0 = make_float4(0.f, 0.f, 0.f, 0.f);
    float4 acc1 = make_float4(0.f, 0.f, 0.f, 0.f);

    int j = beg;
    for (; j + 1 < end; j += 2) {
        int nb0 = __ldg(&csr[j]);
        int nb1 = __ldg(&csr[j + 1]);
        float4 v0 = load_h4_as_f4(feat + (size_t)nb0 * FEAT + lane * 4);
        float4 v1 = load_h4_as_f4(feat + (size_t)nb1 * FEAT + lane * 4);
        acc0.x += v0.x; acc0.y += v0.y; acc0.z += v0.z; acc0.w += v0.w;
        acc1.x += v1.x; acc1.y += v1.y; acc1.z += v1.z; acc1.w += v1.w;
    }
    if (j < end) {
        int nb = __ldg(&csr[j]);
        float4 v = load_h4_as_f4(feat + (size_t)nb * FEAT + lane * 4);
        acc0.x += v.x; acc0.y += v.y; acc0.z += v.z; acc0.w += v.w;
    }

    float iv = invd[node];
    float4 o;
    o.x = (acc0.x + acc1.x) * iv;
    o.y = (acc0.y + acc1.y) * iv;
    o.z = (acc0.z + acc1.z) * iv;
    o.w = (acc0.w + acc1.w) * iv;
    *reinterpret_cast<float4*>(agg + (size_t)node * FEAT + lane * 4) = o;
}

// ---------------- mma.sync SAGE GEMM (bf16 3-chain split, fp32 accum, fp16 I/O) ----------------
// out16[row,j] = relu( agg[row,:] . Wl[j,:] + x16[row,:] . Wr[j,:] + b[j] )
#define PITCHB 272
#define SM_AH  0
#define SM_AL  34816
#define SM_BH  69632
#define SM_BL  104448
#define SM_TOT_MMA 139264

__global__ __launch_bounds__(256, 1) void sage_gemm_mma(
        const float* __restrict__ agg, const __half* __restrict__ x16,
        const float* __restrict__ Wl, const float* __restrict__ Wr,
        const float* __restrict__ b, __half* __restrict__ out16, int n) {
    extern __shared__ char smem[];
    const uint32_t sbase = smem_u32(smem);
    const int tid  = threadIdx.x;
    const int wid  = tid >> 5;
    const int lane = tid & 31;
    const int wr   = wid & 3;      // warp row group: rows [wr*32, wr*32+32)
    const int wc   = wid >> 2;     // warp col group: cols [wc*64, wc*64+64)
    const int grp  = lane >> 2;
    const int tig  = lane & 3;
    const int t8   = lane >> 3;
    const int rr   = lane & 7;
    const int row0 = blockIdx.x * 128;

    const int a_row_part = (t8 & 1) * 8 + rr;
    const uint32_t a_koff = (uint32_t)((t8 >> 1) * 16);
    const int b_row_part = (t8 >> 1) * 8 + rr;
    const uint32_t b_koff = (uint32_t)((t8 & 1) * 16);

    float D[2][8][4];
#pragma unroll
    for (int mt = 0; mt < 2; mt++)
#pragma unroll
        for (int nt = 0; nt < 8; nt++)
#pragma unroll
            for (int k = 0; k < 4; k++) D[mt][nt][k] = 0.0f;

#pragma unroll
    for (int phase = 0; phase < 2; phase++) {
        const float* Bsrc = phase ? Wr : Wl;

        __syncthreads();

        // stage A rows (zero-pad past n), split bf16 hi/lo
        for (int i = tid; i < 128 * 32; i += 256) {
            int r = i >> 5, g = i & 31;
            float4 v = make_float4(0.f, 0.f, 0.f, 0.f);
            int row = row0 + r;
            if (row < n) {
                if (phase == 0)
                    v = *reinterpret_cast<const float4*>(agg + (size_t)row * FEAT + g * 4);
                else
                    v = load_h4_as_f4(x16 + (size_t)row * FEAT + g * 4);
            }
            float hx = __bfloat162float(__float2bfloat16_rn(v.x));
            float hy = __bfloat162float(__float2bfloat16_rn(v.y));
            float hz = __bfloat162float(__float2bfloat16_rn(v.z));
            float hw = __bfloat162float(__float2bfloat16_rn(v.w));
            uint2 hi2 = make_uint2(pack_bf16x2(v.x, v.y), pack_bf16x2(v.z, v.w));
            uint2 lo2 = make_uint2(pack_bf16x2(v.x - hx, v.y - hy),
                                   pack_bf16x2(v.z - hz, v.w - hw));
            uint32_t off = (uint32_t)(r * PITCHB + g * 8);
            *reinterpret_cast<uint2*>(smem + SM_AH + off) = hi2;
            *reinterpret_cast<uint2*>(smem + SM_AL + off) = lo2;
        }
        // stage B = weights [n=j][k], split hi/lo
        for (int i = tid; i < 128 * 32; i += 256) {
            int j = i >> 5, g = i & 31;
            float4 v = *reinterpret_cast<const float4*>(Bsrc + (size_t)j * FEAT + g * 4);
            float hx = __bfloat162float(__float2bfloat16_rn(v.x));
            float hy = __bfloat162float(__float2bfloat16_rn(v.y));
            float hz = __bfloat162float(__float2bfloat16_rn(v.z));
            float hw = __bfloat162float(__float2bfloat16_rn(v.w));
            uint2 hi2 = make_uint2(pack_bf16x2(v.x, v.y), pack_bf16x2(v.z, v.w));
            uint2 lo2 = make_uint2(pack_bf16x2(v.x - hx, v.y - hy),
                                   pack_bf16x2(v.z - hz, v.w - hw));
            uint32_t off = (uint32_t)(j * PITCHB + g * 8);
            *reinterpret_cast<uint2*>(smem + SM_BH + off) = hi2;
            *reinterpret_cast<uint2*>(smem + SM_BL + off) = lo2;
        }
        __syncthreads();

#pragma unroll
        for (int ks = 0; ks < 8; ks++) {
            const uint32_t k0b = (uint32_t)(ks * 32);

            uint32_t ahi[2][4], alo[2][4];
#pragma unroll
            for (int mt = 0; mt < 2; mt++) {
                uint32_t addr = sbase + SM_AH
                              + (uint32_t)((wr * 32 + mt * 16 + a_row_part) * PITCHB)
                              + k0b + a_koff;
                ldsm_x4(ahi[mt], addr);
                ldsm_x4(alo[mt], addr + (SM_AL - SM_AH));
            }

            uint32_t bhi[8][2], blo[8][2];
#pragma unroll
            for (int nq = 0; nq < 4; nq++) {
                uint32_t addr = sbase + SM_BH
                              + (uint32_t)((wc * 64 + nq * 16 + b_row_part) * PITCHB)
                              + k0b + b_koff;
                uint32_t r4[4];
                ldsm_x4(r4, addr);
                bhi[nq * 2][0] = r4[0]; bhi[nq * 2][1] = r4[1];
                bhi[nq * 2 + 1][0] = r4[2]; bhi[nq * 2 + 1][1] = r4[3];
                ldsm_x4(r4, addr + (SM_BL - SM_BH));
                blo[nq * 2][0] = r4[0]; blo[nq * 2][1] = r4[1];
                blo[nq * 2 + 1][0] = r4[2]; blo[nq * 2 + 1][1] = r4[3];
            }

#pragma unroll
            for (int mt = 0; mt < 2; mt++)
#pragma unroll
                for (int nt = 0; nt < 8; nt++) {
                    mma_bf16(D[mt][nt], ahi[mt], bhi[nt][0], bhi[nt][1]);
                    mma_bf16(D[mt][nt], ahi[mt], blo[nt][0], blo[nt][1]);
                    mma_bf16(D[mt][nt], alo[mt], bhi[nt][0], bhi[nt][1]);
                }
        }
    }

    // epilogue: bias + relu -> fp16 stores
#pragma unroll
    for (int mt = 0; mt < 2; mt++) {
        int row_lo = row0 + wr * 32 + mt * 16 + grp;
        int row_hi = row_lo + 8;
#pragma unroll
        for (int nt = 0; nt < 8; nt++) {
            int c0 = wc * 64 + nt * 8 + tig * 2;
            float bx = __ldg(b + c0);
            float by = __ldg(b + c0 + 1);
            if (row_lo < n) {
                __half2 o = __floats2half2_rn(fmaxf(D[mt][nt][0] + bx, 0.0f),
                                              fmaxf(D[mt][nt][1] + by, 0.0f));
                *reinterpret_cast<uint32_t*>(out16 + (size_t)row_lo * FEAT + c0) =
                    reinterpret_cast<uint32_t&>(o);
            }
            if (row_hi < n) {
                __half2 o = __floats2half2_rn(fmaxf(D[mt][nt][2] + bx, 0.0f),
                                              fmaxf(D[mt][nt][3] + by, 0.0f));
                *reinterpret_cast<uint32_t*>(out16 + (size_t)row_hi * FEAT + c0) =
                    reinterpret_cast<uint32_t&>(o);
            }
        }
    }
}

// ---------------- head projection: y = h @ W^T for 8 channels, warp per node (fp16 h) ----------------
__global__ void project_kernel(const __half* __restrict__ h,
                               const float* __restrict__ Wal, const float* __restrict__ War, const float* __restrict__ ba,
                               const float* __restrict__ Wsl, const float* __restrict__ Wsr, const float* __restrict__ bs,
                               const float* __restrict__ Wel, const float* __restrict__ Wer, const float* __restrict__ be,
                               float* __restrict__ yl, float* __restrict__ yr, int n) {
    __shared__ float WL[8][128];
    __shared__ float WR[8][128];
    __shared__ float bias[8];
    const int tid = threadIdx.x;

    for (int i = tid; i < 3 * 128; i += blockDim.x) { WL[i >> 7][i & 127] = Wal[i]; WR[i >> 7][i & 127] = War[i]; }
    for (int i = tid; i < 2 * 128; i += blockDim.x) { WL[3 + (i >> 7)][i & 127] = Wsl[i]; WR[3 + (i >> 7)][i & 127] = Wsr[i]; }
    for (int i = tid; i < 3 * 128; i += blockDim.x) { WL[5 + (i >> 7)][i & 127] = Wel[i]; WR[5 + (i >> 7)][i & 127] = Wer[i]; }
    if (tid < 3) bias[tid] = ba[tid];
    if (tid < 2) bias[3 + tid] = bs[tid];
    if (tid >= 32 && tid < 35) bias[5 + (tid - 32)] = be[tid - 32];
    __syncthreads();

    const int lane = tid & 31;
    const int wid  = tid >> 5;
    const int node = blockIdx.x * (blockDim.x >> 5) + wid;
    if (node >= n) return;

    float4 xv = load_h4_as_f4(h + (size_t)node * FEAT + lane * 4);

    float accl[8], accr[8];
#pragma unroll
    for (int j = 0; j < 8; j++) {
        const float* wl = &WL[j][lane * 4];
        const float* wr = &WR[j][lane * 4];
        accl[j] = xv.x * wl[0] + xv.y * wl[1] + xv.z * wl[2] + xv.w * wl[3];
        accr[j] = xv.x * wr[0] + xv.y * wr[1] + xv.z * wr[2] + xv.w * wr[3];
#pragma unroll
        for (int off = 16; off > 0; off >>= 1) {
            accl[j] += __shfl_xor_sync(0xFFFFFFFF, accl[j], off);
            accr[j] += __shfl_xor_sync(0xFFFFFFFF, accr[j], off);
        }
    }

    if (lane == 0) {
#pragma unroll
        for (int j = 0; j < 8; j++) {
            yl[(size_t)node * 8 + j] = accl[j];
            yr[(size_t)node * 8 + j] = accr[j] + bias[j];
        }
    }
}

// ---------------- head gather: thread per node, 8-dim mean + root term ----------------
__global__ __launch_bounds__(256) void head_gather_kernel(
        const float* __restrict__ yl, const float* __restrict__ yr,
        const int* __restrict__ csr, const int* __restrict__ off,
        const float* __restrict__ invd, float* __restrict__ out, int n) {
    int node = blockIdx.x * blockDim.x + threadIdx.x;
    if (node >= n) return;

    int beg = off[node];
    int end = off[node + 1];

    float4 s0 = make_float4(0.f, 0.f, 0.f, 0.f);
    float4 s1 = make_float4(0.f, 0.f, 0.f, 0.f);
    for (int e = beg; e < end; e++) {
        int s = __ldg(&csr[e]);
        const float4* p = reinterpret_cast<const float4*>(yl + (size_t)s * 8);
        float4 v0 = p[0], v1 = p[1];
        s0.x += v0.x; s0.y += v0.y; s0.z += v0.z; s0.w += v0.w;
        s1.x += v1.x; s1.y += v1.y; s1.z += v1.z; s1.w += v1.w;
    }

    float iv = invd[node];
    const float4* rp = reinterpret_cast<const float4*>(yr + (size_t)node * 8);
    float4 r0 = rp[0], r1 = rp[1];
    float o0 = s0.x * iv + r0.x;
    float o1 = s0.y * iv + r0.y;
    float o2 = s0.z * iv + r0.z;
    float o3 = s0.w * iv + r0.w;
    float o4 = s1.x * iv + r1.x;
    float o5 = s1.y * iv + r1.y;
    float o6 = s1.z * iv + r1.z;
    float o7 = s1.w * iv + r1.w;

    out[(size_t)node * 3 + 0] = o0;
    out[(size_t)node * 3 + 1] = o1;
    out[(size_t)node * 3 + 2] = o2;
    float* sex = out + (size_t)n * 3;
    sex[(size_t)node * 2 + 0] = o3;
    sex[(size_t)node * 2 + 1] = o4;
    float* eth = out + (size_t)n * 5;
    eth[(size_t)node * 3 + 0] = o5;
    eth[(size_t)node * 3 + 1] = o6;
    eth[(size_t)node * 3 + 2] = o7;
}

// ---------------- launch ----------------
extern "C" void kernel_launch(void* const* d_in, const int* in_sizes, int n_in,
                              void* d_out, int out_size) {
    const float* x  = (const float*)d_in[0];
    const int*   ei = (const int*)d_in[1];
    const float *W1l = (const float*)d_in[2],  *W1r = (const float*)d_in[3],  *b1 = (const float*)d_in[4];
    const float *W2l = (const float*)d_in[5],  *W2r = (const float*)d_in[6],  *b2 = (const float*)d_in[7];
    const float *W3l = (const float*)d_in[8],  *W3r = (const float*)d_in[9],  *b3 = (const float*)d_in[10];
    const float *Wal = (const float*)d_in[11], *War = (const float*)d_in[12], *ba = (const float*)d_in[13];
    const float *Wsl = (const float*)d_in[14], *Wsr = (const float*)d_in[15], *bs = (const float*)d_in[16];
    const float *Wel = (const float*)d_in[17], *Wer = (const float*)d_in[18], *be = (const float*)d_in[19];
    float* out = (float*)d_out;

    const int N = in_sizes[0] / FEAT;
    const int E = in_sizes[1] / 2;
    const int* srcIdx = ei;
    const int* dstIdx = ei + E;

    float *agg, *invd, *yl, *yr;
    __half *x16, *hA, *hB;
    int *degi, *off, *pos, *bsum, *csr;
    cudaGetSymbolAddress((void**)&agg,  g_agg);
    cudaGetSymbolAddress((void**)&x16,  g_x16);
    cudaGetSymbolAddress((void**)&hA,   g_h16A);
    cudaGetSymbolAddress((void**)&hB,   g_h16B);
    cudaGetSymbolAddress((void**)&invd, g_invd);
    cudaGetSymbolAddress((void**)&degi, g_degi);
    cudaGetSymbolAddress((void**)&off,  g_off);
    cudaGetSymbolAddress((void**)&pos,  g_pos);
    cudaGetSymbolAddress((void**)&bsum, g_bsum);
    cudaGetSymbolAddress((void**)&csr,  g_csr);
    cudaGetSymbolAddress((void**)&yl,   g_yl);
    cudaGetSymbolAddress((void**)&yr,   g_yr);

    cudaFuncSetAttribute(sage_gemm_mma, cudaFuncAttributeMaxDynamicSharedMemorySize, SM_TOT_MMA);

    // convert input features to fp16 once
    const int n4 = N * FEAT / 4;
    cvt16_kernel<<<(n4 + 255) / 256, 256>>>(x, x16, n4);

    // ---- CSR build ----
    const int nb = (N + 1023) / 1024;
    cudaMemsetAsync(degi, 0, (size_t)N * sizeof(int));
    hist_kernel<<<(E + 255) / 256, 256>>>(dstIdx, degi, E);
    scan1_kernel<<<nb, 1024>>>(degi, off, bsum, N);
    scan2_kernel<<<1, 128>>>(bsum, nb);
    scan3_kernel<<<(N + 255) / 256, 256>>>(off, bsum, pos, degi, invd, N, E);
    fill_kernel<<<(E + 255) / 256, 256>>>(srcIdx, dstIdx, pos, csr, E);

    const int gatherBlocks = (int)(((long long)N * 32 + 255) / 256);
    const int gemmBlocks = (N + 127) / 128;

    // layer 1: x16 -> hA
    gather16_kernel<<<gatherBlocks, 256>>>(x16, agg, csr, off, invd, N);
    sage_gemm_mma<<<gemmBlocks, 256, SM_TOT_MMA>>>(agg, x16, W1l, W1r, b1, hA, N);

    // layer 2: hA -> hB
    gather16_kernel<<<gatherBlocks, 256>>>(hA, agg, csr, off, invd, N);
    sage_gemm_mma<<<gemmBlocks, 256, SM_TOT_MMA>>>(agg, hA, W2l, W2r, b2, hB, N);

    // layer 3: hB -> hA
    gather16_kernel<<<gatherBlocks, 256>>>(hB, agg, csr, off, invd, N);
    sage_gemm_mma<<<gemmBlocks, 256, SM_TOT_MMA>>>(agg, hB, W3l, W3r, b3, hA, N);

    // heads: project h3 (fp16) to 8 dims, then 8-dim gather-mean
    project_kernel<<<(N + 7) / 8, 256>>>(hA, Wal, War, ba, Wsl, Wsr, bs, Wel, Wer, be,
                                         yl, yr, N);
    head_gather_kernel<<<(N + 255) / 256, 256>>>(yl, yr, csr, off, invd, out, N);
}